// round 14
// baseline (speedup 1.0000x reference)
#include <cuda_runtime.h>
#include <cstdint>
#include <math.h>

#define BB 16
#define TT 200
#define UU 100
#define U1 101
#define V1 129
#define ST 104                    // padded row stride (floats, mult of 8)
#define RR 8                      // rows per warp in lsm
#define NCHUNK 25                 // TT/8 row-chunks
#define LOG2E 1.4426950408889634f
#define LN2   0.6931471805599453f
#define NINF  (-INFINITY)

// Scratch: LINEAR softmax probs, padded stride. Label table shifted +1 col.
// Zero-init globals: unwritten rows/cols are load-bearing guards.
__device__ __align__(16) float g_blank[BB * TT * ST];
__device__ __align__(16) float g_label[BB * TT * ST];
__device__ float    g_loss[BB];
__device__ unsigned g_cnt;
__device__ unsigned g_rdy[BB * NCHUNK];   // per (batch, chunk) producer counters

__device__ __forceinline__ float ex2f_raw(float x) {
    float y; asm("ex2.approx.f32 %0, %1;" : "=f"(y) : "f"(x)); return y;
}
__device__ __forceinline__ float lg2f_raw(float x) {
    float y; asm("lg2.approx.f32 %0, %1;" : "=f"(y) : "f"(x)); return y;
}
__device__ __forceinline__ float rcpf_raw(float x) {
    float y; asm("rcp.approx.f32 %0, %1;" : "=f"(y) : "f"(x)); return y;
}
__device__ __forceinline__ void cp_async16(unsigned int saddr, const void* gaddr) {
    asm volatile("cp.async.cg.shared.global [%0], [%1], 16;"
                 :: "r"(saddr), "l"(gaddr));
}
__device__ __forceinline__ void st_release_shared(unsigned int saddr, int v) {
    asm volatile("st.release.cta.shared.u32 [%0], %1;" :: "r"(saddr), "r"(v));
}
__device__ __forceinline__ int ld_acquire_shared(unsigned int saddr) {
    int v; asm volatile("ld.acquire.cta.shared.u32 %0, [%1];" : "=r"(v) : "r"(saddr));
    return v;
}

// ---------------------------------------------------------------------------
// Kernel 1 (producer): softmax. grid=(2,T,B). Warp handles 8 u-rows.
// No early returns: every block increments its (b, t>>3) chunk counter.
// ---------------------------------------------------------------------------
__global__ void __launch_bounds__(256) lsm_kernel(
    const float* __restrict__ logits,
    const int*   __restrict__ labels,
    const int*   __restrict__ logit_lens,
    const int*   __restrict__ y_lens)
{
    const unsigned FULL = 0xffffffffu;
    int b = blockIdx.z;
    int t = blockIdx.y;
    int tl = __ldg(&logit_lens[b]);
    int yl = __ldg(&y_lens[b]);

    int warp = threadIdx.x >> 5;
    int lane = threadIdx.x & 31;
    int u_base = (blockIdx.x * 8 + warp) * RR;

    if (t < tl && u_base <= yl) {
        int rowbase = (b * TT + t) * U1;

        float v[RR][4];
        #pragma unroll
        for (int r = 0; r < RR; r++) {
            int uc = u_base + r; uc = uc > yl ? yl : uc;
            const float* rp = logits + (size_t)(rowbase + uc) * V1;
            v[r][0] = rp[lane];
            v[r][1] = rp[lane + 32];
            v[r][2] = rp[lane + 64];
            v[r][3] = rp[lane + 96];
        }
        float e4v;
        {
            int uct = u_base + (lane & 7); uct = uct > yl ? yl : uct;
            float t128 = __ldg(logits + (size_t)(rowbase + uct) * V1 + 128);
            e4v = ex2f_raw(t128 * LOG2E);
        }

        float s[RR], lv[RR], b0[RR];
        #pragma unroll
        for (int r = 0; r < RR; r++) {
            float e0 = ex2f_raw(v[r][0] * LOG2E);
            float e1 = ex2f_raw(v[r][1] * LOG2E);
            float e2 = ex2f_raw(v[r][2] * LOG2E);
            float e3 = ex2f_raw(v[r][3] * LOG2E);
            s[r]  = ((e0 + e1) + (e2 + e3)) + ((lane == r) ? e4v : 0.0f);
            b0[r] = e0;
            int u  = u_base + r; u = u > yl ? yl : u;
            int uc = u < UU ? u : UU - 1;
            int lab  = __ldg(&labels[b * UU + uc]);
            int slot = lab >> 5;
            int src  = (slot == 4) ? r : (lab & 31);
            float vsel = (slot == 0) ? e0 :
                         (slot == 1) ? e1 :
                         (slot == 2) ? e2 :
                         (slot == 3) ? e3 : e4v;
            lv[r] = __shfl_sync(FULL, vsel, src);
        }

        #pragma unroll
        for (int o = 16; o > 0; o >>= 1) {
            #pragma unroll
            for (int r = 0; r < RR; r++)
                s[r] += __shfl_xor_sync(FULL, s[r], o);
        }

        int outbase = (b * TT + t) * ST;
        #pragma unroll
        for (int r = 0; r < RR; r++) {
            int u = u_base + r;
            if (u > yl || u >= U1) continue;   // warp-uniform
            float rinv = rcpf_raw(s[r]);
            if (lane == 0) {
                if (u < UU) g_label[outbase + u + 1] = lv[r] * rinv;
                g_blank[outbase + u] = b0[r] * rinv;
            }
        }
        if (lane == 0) __threadfence();        // release stores
    }

    __syncthreads();
    if (threadIdx.x == 0) {
        __threadfence();
        atomicAdd(&g_rdy[b * NCHUNK + (t >> 3)], 1u);
    }
}

// ---------------------------------------------------------------------------
// Kernel 2 (consumer): wavefront DP. Runs CONCURRENTLY with lsm.
// Warp 1 = loader: per chunk, spins on g_rdy, cp.asyncs 8 rows of both
// tables, publishes SMEM watermark. Warp 0 = compute: R12's proven loop,
// polling the watermark before each step's tail loads.
// ---------------------------------------------------------------------------
__global__ void __launch_bounds__(128) dp_kernel(
    const int* __restrict__ logit_lens,
    const int* __restrict__ y_lens,
    float* __restrict__ out)
{
    extern __shared__ float sm[];
    float* sB = sm + 1024;                // front guard sm[192..1023]; wm at sm[0]
    float* sL = sB + TT * ST;

    int b   = blockIdx.x;
    int tid = threadIdx.x;
    int wid = tid >> 5;
    int lane = tid & 31;
    int tl  = logit_lens[b];
    int yl  = y_lens[b];

    unsigned wma = (unsigned)__cvta_generic_to_shared(sm);   // watermark addr

    // init: zero guard region (incl. watermark), zero sB tail rows 193..199
    // (read via the negative-L path before chunk 24 arrives), plant seeds.
    for (int i = tid; i < 1024; i += 128) sm[i] = 0.0f;
    for (int i = tid; i < 7 * ST; i += 128) sB[193 * ST + i] = 0.0f;
    __syncthreads();
    if (tid < 8) sB[-ST * (tid + 1)] = 1.0f;   // seed col0, guard rows -1..-8
    __syncthreads();

    if (wid == 1) {
        // ---------------- loader warp ----------------
        unsigned sBa = (unsigned)__cvta_generic_to_shared(sB);
        unsigned sLa = (unsigned)__cvta_generic_to_shared(sL);
        for (int c = 0; c < NCHUNK; c++) {
            if (lane == 0) {
                volatile unsigned* p = &g_rdy[b * NCHUNK + c];
                while (*p < 16u) __nanosleep(128);
                *p = 0u;                        // reset for next replay
                __threadfence();                // acquire producers' stores
            }
            __syncwarp();
            const float4* srcB = (const float4*)(g_blank + (size_t)b * TT * ST + c * 8 * ST);
            const float4* srcL = (const float4*)(g_label + (size_t)b * TT * ST + c * 8 * ST);
            unsigned offb = sBa + c * 8 * ST * 4;
            unsigned offl = sLa + c * 8 * ST * 4;
            for (int i = lane; i < (8 * ST) / 4; i += 32) {   // 208 float4 per table
                cp_async16(offb + i * 16, srcB + i);
                cp_async16(offl + i * 16, srcL + i);
            }
            asm volatile("cp.async.commit_group;");
            asm volatile("cp.async.wait_group 0;");
            __syncwarp();
            if (lane == 0) st_release_shared(wma, c + 1);
        }
    } else if (wid == 0) {
        // ---------------- compute warp (R12 loop + watermark polls) ----------
        const unsigned FULL = 0xffffffffu;
        int u0    = lane * 4;
        int tlast = tl - 1;
        int pad   = 7 - (tlast & 7);
        int t8max = (tlast >> 3) * 8;
        int laneyl = yl >> 2, cyl = yl & 3;
        int sfin  = laneyl + (tlast >> 3);
        int S     = sfin + 1;
        float fzero = (lane == 0) ? 0.0f : 1.0f;

        float c0 = (lane == 0) ? 1.0f : 0.0f;
        float c1 = 0.f, c2 = 0.f, c3 = 0.f;
        float bnd[8];
        #pragma unroll
        for (int k = 0; k < 8; k++) bnd[k] = 0.f;
        int   Mi = 0, Ml = 0;
        bool  dead = (lane != 0);
        float finL = 1.f; int finM = 0;

        while (ld_acquire_shared(wma) < 1) { }   // chunk 0

        float4 Bc[8], Lc[8];
        {
            int ib = (-pad - 1) * ST + u0;
            int il = (-pad) * ST + u0;
            #pragma unroll
            for (int k = 0; k < 8; k++) {
                Bc[k] = *(const float4*)(sB + ib + k * ST);
                Lc[k] = *(const float4*)(sL + il + k * ST);
            }
        }

        for (int s = 0; s < S; s++) {
            int  Mn = dead ? Ml : Mi;
            int  dM = Ml - Mn;
            dM = dM < -126 ? -126 : (dM > 126 ? 126 : dM);
            float f = __int_as_float((127 + dM) << 23) * fzero;
            Mi = Mn;
            int Mln = __shfl_up_sync(FULL, Mn, 1);
            #pragma unroll
            for (int k = 0; k < 8; k++) bnd[k] *= f;

            float v0 = c0, v1 = c1, v2 = c2, v3 = c3;
            #pragma unroll
            for (int r = 0; r < 8; r++) {
                float w0 = fmaf(v0, Bc[r].x, bnd[r] * Lc[r].x);
                float w1 = fmaf(v1, Bc[r].y, w0 * Lc[r].y);
                float w2 = fmaf(v2, Bc[r].z, w1 * Lc[r].z);
                float w3 = fmaf(v3, Bc[r].w, w2 * Lc[r].w);
                v0 = w0; v1 = w1; v2 = w2; v3 = w3;
                bnd[r] = __shfl_up_sync(FULL, w3, 1);   // raw, frame Mn
            }

            bool hit = (s == sfin) & (lane == laneyl);
            float selc = (cyl == 0) ? v0 : (cyl == 1) ? v1 : (cyl == 2) ? v2 : v3;
            finL = hit ? selc : finL;
            finM = hit ? Mi   : finM;

            float cmax = fmaxf(fmaxf(v0, v1), fmaxf(v2, v3));
            int ebits = __float_as_int(cmax) >> 23;
            dead = (ebits == 0);
            int  se = dead ? 127 : (254 - ebits);
            float sc = __int_as_float(se << 23);
            Mi += dead ? 0 : (ebits - 127);
            c0 = v0 * sc; c1 = v1 * sc; c2 = v2 * sc; c3 = v3 * sc;
            Ml = Mln;

            // wait for chunk s+1 (max row touched next: 8(s+2)-1)
            int need = s + 2; need = need > NCHUNK ? NCHUNK : need;
            while (ld_acquire_shared(wma) < need) { }

            {
                int t0n = 8 * (s + 1 - lane);
                t0n = t0n < 0 ? 0 : (t0n > t8max ? t8max : t0n);
                int ibn = (t0n - pad - 1) * ST + u0;
                int iln = (t0n - pad) * ST + u0;
                #pragma unroll
                for (int k = 0; k < 8; k++) {
                    Bc[k] = *(const float4*)(sB + ibn + k * ST);
                    Lc[k] = *(const float4*)(sL + iln + k * ST);
                }
            }
        }

        float fL = __shfl_sync(FULL, finL, laneyl);
        int   fM = __shfl_sync(FULL, finM, laneyl);
        if (lane == 0) {
            float total2 = lg2f_raw(fL) + (float)fM + lg2f_raw(sB[tlast * ST + yl]);
            float loss = -total2 * LN2 / (float)yl;
            g_loss[b] = loss;
            __threadfence();
            unsigned ticket = atomicAdd(&g_cnt, 1);
            if (ticket == BB - 1) {
                __threadfence();
                float ssum = 0.0f;
                #pragma unroll
                for (int i = 0; i < BB; i++) ssum += g_loss[i];
                out[0] = ssum / (float)BB;
                g_cnt = 0;
            }
        }
    }
    // warps 2,3 simply exit
}

extern "C" void kernel_launch(void* const* d_in, const int* in_sizes, int n_in,
                              void* d_out, int out_size)
{
    const float* logits     = (const float*)d_in[0];
    const int*   labels     = (const int*)d_in[1];
    const int*   logit_lens = (const int*)d_in[2];
    const int*   y_lens     = (const int*)d_in[3];
    float* out = (float*)d_out;

    static cudaStream_t sP = nullptr, sC = nullptr;
    static cudaEvent_t  eF = nullptr, eP = nullptr, eC = nullptr;
    size_t smem = (size_t)(1024 + 2 * TT * ST) * sizeof(float);
    if (!sP) {    // first call is the uncaptured correctness run
        cudaStreamCreateWithFlags(&sP, cudaStreamNonBlocking);
        cudaStreamCreateWithFlags(&sC, cudaStreamNonBlocking);
        cudaEventCreateWithFlags(&eF, cudaEventDisableTiming);
        cudaEventCreateWithFlags(&eP, cudaEventDisableTiming);
        cudaEventCreateWithFlags(&eC, cudaEventDisableTiming);
        cudaFuncSetAttribute(dp_kernel, cudaFuncAttributeMaxDynamicSharedMemorySize, (int)smem);
    }

    // fork from the caller's (capture) stream
    cudaEventRecord(eF, 0);
    cudaStreamWaitEvent(sP, eF, 0);
    cudaStreamWaitEvent(sC, eF, 0);

    dim3 grid(2, TT, BB);
    lsm_kernel<<<grid, 256, 0, sP>>>(logits, labels, logit_lens, y_lens);   // producer first
    dp_kernel<<<BB, 128, smem, sC>>>(logit_lens, y_lens, out);              // consumer

    // join back
    cudaEventRecord(eP, sP);
    cudaEventRecord(eC, sC);
    cudaStreamWaitEvent(0, eP, 0);
    cudaStreamWaitEvent(0, eC, 0);
}

// round 15
// speedup vs baseline: 2.0831x; 2.0831x over previous
#include <cuda_runtime.h>
#include <cstdint>
#include <math.h>

#define BB 16
#define TT 200
#define UU 100
#define U1 101
#define V1 129
#define ST 104                    // padded row stride (mult of 8 -> float4 aligned)
#define RR 8                      // rows per warp in lsm
#define LOG2E 1.4426950408889634f
#define LN2   0.6931471805599453f
#define NINF  (-INFINITY)

// Scratch: LINEAR softmax probs, padded stride. Label table shifted +1 col.
// Zero-init device globals: unwritten rows/cols are load-bearing guards.
__device__ __align__(16) float g_blank[BB * TT * ST];
__device__ __align__(16) float g_label[BB * TT * ST];
__device__ float    g_loss[BB];
__device__ unsigned g_cnt;

__device__ __forceinline__ float ex2f_raw(float x) {
    float y; asm("ex2.approx.f32 %0, %1;" : "=f"(y) : "f"(x)); return y;
}
__device__ __forceinline__ float lg2f_raw(float x) {
    float y; asm("lg2.approx.f32 %0, %1;" : "=f"(y) : "f"(x)); return y;
}
__device__ __forceinline__ float rcpf_raw(float x) {
    float y; asm("rcp.approx.f32 %0, %1;" : "=f"(y) : "f"(x)); return y;
}
__device__ __forceinline__ void cp_async16(unsigned int saddr, const void* gaddr) {
    asm volatile("cp.async.cg.shared.global [%0], [%1], 16;"
                 :: "r"(saddr), "l"(gaddr));
}

// ---------------------------------------------------------------------------
// Kernel 1: softmax. grid=(2,T,B). Warp handles 8 u-rows. Element-128 tail
// handled by ONE lane-parallel load + ONE ex2. LINEAR prob outputs.
// ---------------------------------------------------------------------------
__global__ void __launch_bounds__(256) lsm_kernel(
    const float* __restrict__ logits,
    const int*   __restrict__ labels,
    const int*   __restrict__ logit_lens,
    const int*   __restrict__ y_lens)
{
    const unsigned FULL = 0xffffffffu;
    int b = blockIdx.z;
    int t = blockIdx.y;
    int tl = __ldg(&logit_lens[b]);
    if (t >= tl) return;
    int yl = __ldg(&y_lens[b]);

    int warp = threadIdx.x >> 5;
    int lane = threadIdx.x & 31;
    int u_base = (blockIdx.x * 8 + warp) * RR;
    if (u_base > yl) return;

    int rowbase = (b * TT + t) * U1;

    float v[RR][4];
    #pragma unroll
    for (int r = 0; r < RR; r++) {
        int uc = u_base + r; uc = uc > yl ? yl : uc;
        const float* rp = logits + (size_t)(rowbase + uc) * V1;
        v[r][0] = rp[lane];
        v[r][1] = rp[lane + 32];
        v[r][2] = rp[lane + 64];
        v[r][3] = rp[lane + 96];
    }
    float e4v;
    {
        int uct = u_base + (lane & 7); uct = uct > yl ? yl : uct;
        float t128 = __ldg(logits + (size_t)(rowbase + uct) * V1 + 128);
        e4v = ex2f_raw(t128 * LOG2E);
    }

    float s[RR], lv[RR], b0[RR];
    #pragma unroll
    for (int r = 0; r < RR; r++) {
        float e0 = ex2f_raw(v[r][0] * LOG2E);
        float e1 = ex2f_raw(v[r][1] * LOG2E);
        float e2 = ex2f_raw(v[r][2] * LOG2E);
        float e3 = ex2f_raw(v[r][3] * LOG2E);
        s[r]  = ((e0 + e1) + (e2 + e3)) + ((lane == r) ? e4v : 0.0f);
        b0[r] = e0;
        int u  = u_base + r; u = u > yl ? yl : u;
        int uc = u < UU ? u : UU - 1;
        int lab  = __ldg(&labels[b * UU + uc]);
        int slot = lab >> 5;
        int src  = (slot == 4) ? r : (lab & 31);
        float vsel = (slot == 0) ? e0 :
                     (slot == 1) ? e1 :
                     (slot == 2) ? e2 :
                     (slot == 3) ? e3 : e4v;
        lv[r] = __shfl_sync(FULL, vsel, src);
    }

    #pragma unroll
    for (int o = 16; o > 0; o >>= 1) {
        #pragma unroll
        for (int r = 0; r < RR; r++)
            s[r] += __shfl_xor_sync(FULL, s[r], o);
    }

    int outbase = (b * TT + t) * ST;
    #pragma unroll
    for (int r = 0; r < RR; r++) {
        int u = u_base + r;
        if (u > yl || u >= U1) continue;
        float rinv = rcpf_raw(s[r]);
        if (lane == 0) {
            if (u < UU) g_label[outbase + u + 1] = lv[r] * rinv;
            g_blank[outbase + u] = b0[r] * rinv;
        }
    }
}

// ---------------------------------------------------------------------------
// Kernel 2: linear-domain wavefront DP, 8x4 blocks. Re-associated cell:
// w_u = fmaf(w_{u-1}, L_u, p_u), p_u = v_u * B_u computed OFF the serial
// path (depends only on previous row) -> 1 FMA/cell critical path.
// ---------------------------------------------------------------------------
__global__ void __launch_bounds__(128) dp_kernel(
    const int* __restrict__ logit_lens,
    const int* __restrict__ y_lens,
    float* __restrict__ out)
{
    extern __shared__ float sm[];
    float* sB = sm + 1024;                // 1024-float zeroed front guard
    float* sL = sB + TT * ST;

    int b   = blockIdx.x;
    int tid = threadIdx.x;
    int tl  = logit_lens[b];

    for (int i = tid; i < 1024; i += 128) sm[i] = 0.0f;
    __syncthreads();
    if (tid < 8) sB[-ST * (tid + 1)] = 1.0f;   // seed col0 in guard rows -1..-8
    {   // cp.async full-table preload (tail zeros are guards)
        const float4* srcB = (const float4*)(g_blank + b * TT * ST);
        const float4* srcL = (const float4*)(g_label + b * TT * ST);
        unsigned int dB = (unsigned int)__cvta_generic_to_shared(sB);
        unsigned int dL = (unsigned int)__cvta_generic_to_shared(sL);
        for (int i = tid; i < (TT * ST) / 4; i += 128) {
            cp_async16(dB + i * 16, srcB + i);
            cp_async16(dL + i * 16, srcL + i);
        }
        asm volatile("cp.async.commit_group;");
        asm volatile("cp.async.wait_group 0;");
    }
    __syncthreads();
    if (tid >= 32) return;

    const unsigned FULL = 0xffffffffu;
    int lane  = tid;
    int u0    = lane * 4;
    int yl    = y_lens[b];
    int tlast = tl - 1;
    int pad   = 7 - (tlast & 7);          // tlast lands on block row 7
    int t8max = (tlast >> 3) * 8;
    int laneyl = yl >> 2, cyl = yl & 3;
    int sfin  = laneyl + (tlast >> 3);
    int S     = sfin + 1;
    float fzero = (lane == 0) ? 0.0f : 1.0f;

    float c0 = (lane == 0) ? 1.0f : 0.0f;
    float c1 = 0.f, c2 = 0.f, c3 = 0.f;
    float bnd[8];
    #pragma unroll
    for (int k = 0; k < 8; k++) bnd[k] = 0.f;
    int   Mi = 0, Ml = 0;
    bool  dead = (lane != 0);
    float finL = 1.f; int finM = 0;

    // initial coefficient load (s=0): t0 clamped to 0 for all lanes
    float4 Bc[8], Lc[8];
    {
        int ib = (-pad - 1) * ST + u0;
        int il = (-pad) * ST + u0;
        #pragma unroll
        for (int k = 0; k < 8; k++) {
            Bc[k] = *(const float4*)(sB + ib + k * ST);
            Lc[k] = *(const float4*)(sL + il + k * ST);
        }
    }

    for (int s = 0; s < S; s++) {
        // --- reconcile; frame shfl for NEXT step issued immediately ---
        int  Mn = dead ? Ml : Mi;
        int  dM = Ml - Mn;
        dM = dM < -126 ? -126 : (dM > 126 ? 126 : dM);
        float f = __int_as_float((127 + dM) << 23) * fzero;
        Mi = Mn;
        int Mln = __shfl_up_sync(FULL, Mn, 1);
        #pragma unroll
        for (int k = 0; k < 8; k++) bnd[k] *= f;

        // --- 8x4 chain, 1 FMA/cell critical path ---
        float v0 = c0, v1 = c1, v2 = c2, v3 = c3;
        #pragma unroll
        for (int r = 0; r < 8; r++) {
            float p0 = v0 * Bc[r].x;      // off-path muls (prev-row values)
            float p1 = v1 * Bc[r].y;
            float p2 = v2 * Bc[r].z;
            float p3 = v3 * Bc[r].w;
            v0 = fmaf(bnd[r], Lc[r].x, p0);
            v1 = fmaf(v0,     Lc[r].y, p1);
            v2 = fmaf(v1,     Lc[r].z, p2);
            v3 = fmaf(v2,     Lc[r].w, p3);
            bnd[r] = __shfl_up_sync(FULL, v3, 1);   // raw, frame Mn
        }

        // --- capture final cell (frame Mi = Mn, pre-rescale) ---
        bool hit = (s == sfin) & (lane == laneyl);
        float selc = (cyl == 0) ? v0 : (cyl == 1) ? v1 : (cyl == 2) ? v2 : v3;
        finL = hit ? selc : finL;
        finM = hit ? Mi   : finM;

        // --- branch-free power-of-2 rescale (carries only) ---
        float cmax = fmaxf(fmaxf(v0, v1), fmaxf(v2, v3));
        int ebits = __float_as_int(cmax) >> 23;
        dead = (ebits == 0);
        int  se = dead ? 127 : (254 - ebits);
        float sc = __int_as_float(se << 23);
        Mi += dead ? 0 : (ebits - 127);
        c0 = v0 * sc; c1 = v1 * sc; c2 = v2 * sc; c3 = v3 * sc;
        Ml = Mln;

        // --- tail loads for step s+1, directly into live registers ---
        {
            int t0n = 8 * (s + 1 - lane);
            t0n = t0n < 0 ? 0 : (t0n > t8max ? t8max : t0n);
            int ibn = (t0n - pad - 1) * ST + u0;
            int iln = (t0n - pad) * ST + u0;
            #pragma unroll
            for (int k = 0; k < 8; k++) {
                Bc[k] = *(const float4*)(sB + ibn + k * ST);
                Lc[k] = *(const float4*)(sL + iln + k * ST);
            }
        }
    }

    float fL = __shfl_sync(FULL, finL, laneyl);
    int   fM = __shfl_sync(FULL, finM, laneyl);
    if (lane == 0) {
        float total2 = lg2f_raw(fL) + (float)fM + lg2f_raw(sB[tlast * ST + yl]);
        float loss = -total2 * LN2 / (float)yl;
        g_loss[b] = loss;
        __threadfence();
        unsigned ticket = atomicAdd(&g_cnt, 1);
        if (ticket == BB - 1) {
            __threadfence();
            float ssum = 0.0f;
            #pragma unroll
            for (int i = 0; i < BB; i++) ssum += g_loss[i];
            out[0] = ssum / (float)BB;
            g_cnt = 0;
        }
    }
}

extern "C" void kernel_launch(void* const* d_in, const int* in_sizes, int n_in,
                              void* d_out, int out_size)
{
    const float* logits     = (const float*)d_in[0];
    const int*   labels     = (const int*)d_in[1];
    const int*   logit_lens = (const int*)d_in[2];
    const int*   y_lens     = (const int*)d_in[3];
    float* out = (float*)d_out;

    dim3 grid(2, TT, BB);                 // 2 blocks x 8 warps x 8 rows >= 101
    lsm_kernel<<<grid, 256>>>(logits, labels, logit_lens, y_lens);

    size_t smem = (size_t)(1024 + 2 * TT * ST) * sizeof(float);
    cudaFuncSetAttribute(dp_kernel, cudaFuncAttributeMaxDynamicSharedMemorySize, (int)smem);
    dp_kernel<<<BB, 128, smem>>>(logit_lens, y_lens, out);
}